// round 14
// baseline (speedup 1.0000x reference)
#include <cuda_runtime.h>
#include <cuda_fp16.h>
#include <cstdint>
#include <math.h>

#define BB 16
#define CC 128
#define NN 16384
#define NTILES 2048
#define CHUNK 14
#define GRID 147
#define SQRTC 11.313708498984761f
#define QSCALE 0.17677669529663688f
#define L2E 1.4426950408889634f

// ---- global scratch ----
__device__ __align__(16) __half g_W16[3][128 * 136];
__device__ __align__(16) __half g_Xh[(size_t)2048 * 17408];
__device__ float g_ctx[BB * 4 * 32 * 32];
__device__ float g_den[BB * CC];

// =============================== helpers ==================================
__device__ __forceinline__ uint32_t smem_u32(const void* p) {
    uint32_t a;
    asm("{ .reg .u64 t; cvta.to.shared.u64 t, %1; cvt.u32.u64 %0, t; }" : "=r"(a) : "l"(p));
    return a;
}
__device__ __forceinline__ void ldsm4(uint32_t addr, uint32_t& r0, uint32_t& r1,
                                      uint32_t& r2, uint32_t& r3) {
    asm volatile("ldmatrix.sync.aligned.m8n8.x4.shared.b16 {%0,%1,%2,%3}, [%4];"
                 : "=r"(r0), "=r"(r1), "=r"(r2), "=r"(r3) : "r"(addr));
}
__device__ __forceinline__ void mma8(float* c, uint32_t a0, uint32_t a1, uint32_t a2,
                                     uint32_t a3, uint32_t b0, uint32_t b1) {
    asm volatile(
        "mma.sync.aligned.m16n8k16.row.col.f32.f16.f16.f32 "
        "{%0,%1,%2,%3},{%4,%5,%6,%7},{%8,%9},{%0,%1,%2,%3};"
        : "+f"(c[0]), "+f"(c[1]), "+f"(c[2]), "+f"(c[3])
        : "r"(a0), "r"(a1), "r"(a2), "r"(a3), "r"(b0), "r"(b1));
}
__device__ __forceinline__ uint32_t exp2_h2(float v0, float v1) {
    __half2 l = __floats2half2_rn(v0, v1);
    uint32_t e;
    asm("ex2.approx.f16x2 %0, %1;" : "=r"(e) : "r"(*(uint32_t*)&l));
    return e;
}
__device__ __forceinline__ void stcs2(float* p, float2 v) {
    asm volatile("st.global.cs.v2.f32 [%0], {%1, %2};" :: "l"(p), "f"(v.x), "f"(v.y));
}
#define CP_ASYNC16(saddr, gptr) \
    asm volatile("cp.async.cg.shared.global [%0], [%1], 16;" :: "r"((uint32_t)(saddr)), "l"(gptr))
#define CP_COMMIT() asm volatile("cp.async.commit_group;" ::: "memory")
#define CP_WAIT0()  asm volatile("cp.async.wait_group 0;" ::: "memory")

template <int KSTEPS, int NT2>
__device__ __forceinline__ void gemm_pass(float* acc, uint32_t aLane, uint32_t bLane) {
    #pragma unroll
    for (int ks = 0; ks < KSTEPS; ks++) {
        uint32_t a0, a1, a2, a3;
        ldsm4(aLane + ks * 32, a0, a1, a2, a3);
        #pragma unroll
        for (int nt = 0; nt < NT2; nt++) {
            uint32_t b0, b1, b2, b3;
            ldsm4(bLane + nt * 4352 + ks * 32, b0, b1, b2, b3);
            mma8(acc + nt * 8,     a0, a1, a2, a3, b0, b1);
            mma8(acc + nt * 8 + 4, a0, a1, a2, a3, b2, b3);
        }
    }
}
template <int KSTEPS, int NT2>
__device__ __forceinline__ void gemm_dual(float* accA, float* accC,
                                          uint32_t aLane, uint32_t cLane, uint32_t bLane) {
    #pragma unroll
    for (int ks = 0; ks < KSTEPS; ks++) {
        uint32_t a0, a1, a2, a3, c0, c1, c2, c3;
        ldsm4(aLane + ks * 32, a0, a1, a2, a3);
        ldsm4(cLane + ks * 32, c0, c1, c2, c3);
        #pragma unroll
        for (int nt = 0; nt < NT2; nt++) {
            uint32_t b0, b1, b2, b3;
            ldsm4(bLane + nt * 4352 + ks * 32, b0, b1, b2, b3);
            mma8(accA + nt * 8,     a0, a1, a2, a3, b0, b1);
            mma8(accA + nt * 8 + 4, a0, a1, a2, a3, b2, b3);
            mma8(accC + nt * 8,     c0, c1, c2, c3, b0, b1);
            mma8(accC + nt * 8 + 4, c0, c1, c2, c3, b2, b3);
        }
    }
}
__device__ __forceinline__ uint32_t a_lane_addr(uint32_t sb, uint32_t off, int m0,
                                                int rs, int lane) {
    return sb + off + (uint32_t)(m0 + (lane & 15)) * rs + ((lane >> 4) << 4);
}
__device__ __forceinline__ uint32_t b_lane_addr(uint32_t sb, uint32_t off, int lane) {
    return sb + off + (uint32_t)((lane & 7) + ((lane & 16) >> 1)) * 272 + ((lane & 8) << 1);
}

// =============================== prep ======================================
__global__ void prep_kernel(const float* __restrict__ wqkv, const float* __restrict__ g1) {
    int i = blockIdx.x * 256 + threadIdx.x;
    if (i < 49152) {
        int g = i >> 14, r = i & 16383, o = r >> 7, c = r & 127;
        float v = wqkv[((g << 7) + o) * CC + c] * g1[c] * SQRTC;
        g_W16[g][o * 136 + c] = __float2half_rn(v);
    }
    if (i < BB * 4096) g_ctx[i] = 0.f;
    if (i < BB * CC)   g_den[i] = 0.f;
}

// =============================== K1 (persistent, chunked) ==================
#define K1_WK   0u
#define K1_WV   34816u
#define K1_X    69632u
#define K1_E    104448u
#define K1_V    139264u
#define K1_SMEM 174080

__global__ __launch_bounds__(512, 1) void qkv_kernel(const float* __restrict__ x) {
    extern __shared__ char sm[];
    const uint32_t sb = smem_u32(sm);
    const int tid = threadIdx.x, lane = tid & 31, w = tid >> 5;

    int idx = blockIdx.x * CHUNK;
    const int end = (idx + CHUNK < NTILES) ? idx + CHUNK : NTILES;
    if (idx >= NTILES) return;

    {
        const uint4* wsrc = (const uint4*)g_W16[1];
        uint4* wdst = (uint4*)(sm + K1_WK);
        for (int i = tid; i < 4352; i += 512) wdst[i] = wsrc[i];
    }
    const int t = tid >> 2, cq = tid & 3;
    const int m0 = (w & 7) << 4, th = w >> 3;
    const int gp = lane >> 2, tq = (lane & 3) << 1;
    const uint32_t bX = b_lane_addr(sb, K1_X + th * 17408u, lane);
    const uint32_t aWk = a_lane_addr(sb, K1_WK, m0, 272, lane);
    const uint32_t aWv = a_lane_addr(sb, K1_WV, m0, 272, lane);

    float xr[32];
    {
        const float* xb = x + ((size_t)(idx >> 7) << 21) + ((idx & 127) << 7) + t;
        #pragma unroll
        for (int j = 0; j < 32; j++) xr[j] = xb[(size_t)(cq * 32 + j) << 14];
    }

    while (true) {
        const int b = idx >> 7;
        float s = 0.f;
        #pragma unroll
        for (int j = 0; j < 32; j++) s = fmaf(xr[j], xr[j], s);
        s += __shfl_xor_sync(0xffffffffu, s, 1);
        s += __shfl_xor_sync(0xffffffffu, s, 2);
        const float it = 1.0f / fmaxf(sqrtf(s), 1e-12f);
        {
            uint32_t vals[16];
            #pragma unroll
            for (int j2 = 0; j2 < 16; j2++) {
                __half2 h = __floats2half2_rn(xr[2 * j2] * it, xr[2 * j2 + 1] * it);
                vals[j2] = *(uint32_t*)&h;
            }
            const uint32_t roff = (uint32_t)t * 272 + ((uint32_t)cq << 6);
            uint4* ps = (uint4*)(sm + K1_X + roff);
            uint4* pg = (uint4*)((char*)g_Xh + (size_t)idx * 34816 + roff);
            const uint4* v4 = (const uint4*)vals;
            #pragma unroll
            for (int j = 0; j < 4; j++) { ps[j] = v4[j]; pg[j] = v4[j]; }
        }
        __syncthreads();   // B1

        float acck[32], accv[32];
        #pragma unroll
        for (int i = 0; i < 32; i++) { acck[i] = 0.f; accv[i] = 0.f; }
        gemm_dual<8, 4>(acck, accv, aWk, aWv, bX);

        // epilogue k
        {
            const int r0 = m0 + gp, r1 = r0 + 8;
            float d0 = 0.f, d1 = 0.f;
            #pragma unroll
            for (int nt = 0; nt < 4; nt++) {
                #pragma unroll
                for (int s2 = 0; s2 < 2; s2++) {
                    int cb = (th << 6) + (nt << 4) + (s2 << 3) + tq;
                    const float* a4 = acck + (nt << 3) + (s2 << 2);
                    uint32_t e0 = exp2_h2(a4[0] * L2E, a4[1] * L2E);
                    uint32_t e1 = exp2_h2(a4[2] * L2E, a4[3] * L2E);
                    *(uint32_t*)(sm + K1_E + r0 * 272 + cb * 2) = e0;
                    *(uint32_t*)(sm + K1_E + r1 * 272 + cb * 2) = e1;
                    float2 f0 = __half22float2(*(__half2*)&e0);
                    float2 f1 = __half22float2(*(__half2*)&e1);
                    d0 += f0.x + f0.y;
                    d1 += f1.x + f1.y;
                }
            }
            d0 += __shfl_xor_sync(0xffffffffu, d0, 1);
            d0 += __shfl_xor_sync(0xffffffffu, d0, 2);
            d1 += __shfl_xor_sync(0xffffffffu, d1, 1);
            d1 += __shfl_xor_sync(0xffffffffu, d1, 2);
            if ((lane & 3) == 0) {
                atomicAdd(&g_den[(b << 7) + r0], d0);
                atomicAdd(&g_den[(b << 7) + r1], d1);
            }
        }
        const int nidx = idx + 1;
        const bool more = nidx < end;
        if (more) {
            const float* xb = x + ((size_t)(nidx >> 7) << 21) + ((nidx & 127) << 7) + t;
            #pragma unroll
            for (int j = 0; j < 32; j++) xr[j] = xb[(size_t)(cq * 32 + j) << 14];
        }
        // epilogue v
        {
            const int r0 = m0 + gp, r1 = r0 + 8;
            #pragma unroll
            for (int nt = 0; nt < 4; nt++) {
                #pragma unroll
                for (int s2 = 0; s2 < 2; s2++) {
                    int cb = (th << 6) + (nt << 4) + (s2 << 3) + tq;
                    const float* a4 = accv + (nt << 3) + (s2 << 2);
                    __half2 h0 = __floats2half2_rn(a4[0], a4[1]);
                    __half2 h1 = __floats2half2_rn(a4[2], a4[3]);
                    *(uint32_t*)(sm + K1_V + r0 * 272 + cb * 2) = *(uint32_t*)&h0;
                    *(uint32_t*)(sm + K1_V + r1 * 272 + cb * 2) = *(uint32_t*)&h1;
                }
            }
        }
        __syncthreads();   // B2
        // gram
        {
            const int h = (w & 7) >> 1;
            float acc16[16];
            #pragma unroll
            for (int i = 0; i < 16; i++) acc16[i] = 0.f;
            uint32_t aE = a_lane_addr(sb, K1_E, m0, 272, lane) + th * 128u;
            uint32_t bV = b_lane_addr(sb, K1_V + h * 8704u, lane) + th * 128u;
            gemm_pass<4, 2>(acc16, aE, bV);

            const int dl0 = (m0 + gp) & 31, dl1 = dl0 + 8;
            float* cbase = g_ctx + (((b << 2) + h) << 10);
            #pragma unroll
            for (int nt = 0; nt < 2; nt++) {
                #pragma unroll
                for (int s2 = 0; s2 < 2; s2++) {
                    int cb = (nt << 4) + (s2 << 3) + tq;
                    const float* a4 = acc16 + (nt << 3) + (s2 << 2);
                    atomicAdd(cbase + (dl0 << 5) + cb,     a4[0]);
                    atomicAdd(cbase + (dl0 << 5) + cb + 1, a4[1]);
                    atomicAdd(cbase + (dl1 << 5) + cb,     a4[2]);
                    atomicAdd(cbase + (dl1 << 5) + cb + 1, a4[3]);
                }
            }
        }
        if (!more) return;
        idx = nidx;
    }
}

// =============================== K2 (reg-softmax, inline G) ================
// regions: WQ@0 | X0@34816 | X1@69632 | G@104448 | BP@139264 (ctxn stage overlay)
//          PS@174080 | BIAS@178176 | G2@178688 | INVS@179200
#define K2_WQ   0u
#define K2_X0   34816u
#define K2_X1   69632u
#define K2_G    104448u
#define K2_BP   139264u
#define K2_PS   174080u
#define K2_BIAS 178176u
#define K2_G2   178688u
#define K2_INVS 179200u
#define K2_SMEM 179712

__global__ __launch_bounds__(512, 1) void out_kernel(const float* __restrict__ wout,
                                                     const float* __restrict__ b_out,
                                                     const float* __restrict__ g2,
                                                     float* __restrict__ out) {
    extern __shared__ char sm[];
    const uint32_t sb = smem_u32(sm);
    const int tid = threadIdx.x, lane = tid & 31, w = tid >> 5;
    float* psm  = (float*)(sm + K2_PS);
    float* invs = (float*)(sm + K2_INVS);
    float* bs   = (float*)(sm + K2_BIAS);
    float* g2s  = (float*)(sm + K2_G2);

    int idx = blockIdx.x * CHUNK;
    const int end = (idx + CHUNK < NTILES) ? idx + CHUNK : NTILES;
    if (idx >= NTILES) return;

    {
        const uint4* wsrc = (const uint4*)g_W16[0];
        uint4* wdst = (uint4*)(sm + K2_WQ);
        for (int i = tid; i < 2176; i += 512) wdst[i] = wsrc[i];
        if (tid < 128) { bs[tid] = b_out[tid]; g2s[tid] = g2[tid]; }
    }
    const int m0 = (w & 7) << 4, th = w >> 3;
    const int gp = lane >> 2, tq = (lane & 3) << 1;
    const uint32_t aG  = a_lane_addr(sb, K2_G,  m0, 272, lane);
    const uint32_t bWq = b_lane_addr(sb, K2_WQ + th * 17408u, lane);

    uint32_t xoff = K2_X0;
    int prev_b = -1;
    {
        const uint4* src = (const uint4*)g_Xh + (size_t)idx * 2176;
        for (int i = tid; i < 2176; i += 512)
            CP_ASYNC16(sb + K2_X0 + (uint32_t)i * 16, src + i);
        CP_COMMIT();
    }

    while (true) {
        const int b = idx >> 7, p0 = (idx & 127) << 7;
        if (b != prev_b) {
            // stage ctxn (fp32) in BP region, compute G = Wo * ctxn -> K2_G
            float* ctxn = (float*)(sm + K2_BP);
            #pragma unroll
            for (int jj = 0; jj < 8; jj++) {
                int j = tid + (jj << 9);
                ctxn[j] = __ldcg(&g_ctx[(b << 12) + j]) / __ldcg(&g_den[(b << 7) + (j >> 5)]);
            }
            __syncthreads();
            {
                const int o = tid >> 2, h = tid & 3;
                float4 wr[8];
                const float4* wsrc = (const float4*)(wout + (o << 7) + (h << 5));
                #pragma unroll
                for (int j = 0; j < 8; j++) wr[j] = wsrc[j];
                const float* chd = ctxn + (h << 10);
                #pragma unroll
                for (int d = 0; d < 32; d++) {
                    const float4* cr = (const float4*)(chd + (d << 5));
                    float a = 0.f;
                    #pragma unroll
                    for (int j = 0; j < 8; j++) {
                        float4 c4 = cr[j];
                        a = fmaf(wr[j].x, c4.x, a);
                        a = fmaf(wr[j].y, c4.y, a);
                        a = fmaf(wr[j].z, c4.z, a);
                        a = fmaf(wr[j].w, c4.w, a);
                    }
                    *(__half*)(sm + K2_G + (uint32_t)o * 272 + (((h << 5) + d) << 1)) =
                        __float2half_rn(a);
                }
            }
            prev_b = b;
        }
        CP_WAIT0();
        __syncthreads();   // B1: X + G visible; prior Bp reads drained; ctxn reads done

        // ---- GEMM q (A = X tokens-as-rows, B = Wq) -> logits in regs ----
        float acc[32];
        #pragma unroll
        for (int i = 0; i < 32; i++) acc[i] = 0.f;
        gemm_pass<8, 4>(acc, a_lane_addr(sb, xoff, m0, 272, lane), bWq);

        // ---- register softmax over d ----
        {
            const int r0 = m0 + gp, r1 = r0 + 8;
            float mx[2][2] = {{-1e30f, -1e30f}, {-1e30f, -1e30f}};
            #pragma unroll
            for (int nt = 0; nt < 4; nt++) {
                const int hl = nt >> 1;
                #pragma unroll
                for (int s2 = 0; s2 < 2; s2++) {
                    const float* a4 = acc + (nt << 3) + (s2 << 2);
                    mx[0][hl] = fmaxf(mx[0][hl], fmaxf(a4[0], a4[1]));
                    mx[1][hl] = fmaxf(mx[1][hl], fmaxf(a4[2], a4[3]));
                }
            }
            #pragma unroll
            for (int r = 0; r < 2; r++)
                #pragma unroll
                for (int hl = 0; hl < 2; hl++) {
                    mx[r][hl] = fmaxf(mx[r][hl], __shfl_xor_sync(0xffffffffu, mx[r][hl], 1));
                    mx[r][hl] = fmaxf(mx[r][hl], __shfl_xor_sync(0xffffffffu, mx[r][hl], 2));
                }
            uint32_t eh[16];
            float sum[2][2] = {{0.f, 0.f}, {0.f, 0.f}};
            #pragma unroll
            for (int nt = 0; nt < 4; nt++) {
                const int hl = nt >> 1;
                #pragma unroll
                for (int s2 = 0; s2 < 2; s2++) {
                    const float* a4 = acc + (nt << 3) + (s2 << 2);
                    const int ei = (nt << 2) + (s2 << 1);
                    eh[ei]     = exp2_h2((a4[0] - mx[0][hl]) * L2E, (a4[1] - mx[0][hl]) * L2E);
                    eh[ei + 1] = exp2_h2((a4[2] - mx[1][hl]) * L2E, (a4[3] - mx[1][hl]) * L2E);
                    float2 f0 = __half22float2(*(__half2*)&eh[ei]);
                    float2 f1 = __half22float2(*(__half2*)&eh[ei + 1]);
                    sum[0][hl] += f0.x + f0.y;
                    sum[1][hl] += f1.x + f1.y;
                }
            }
            #pragma unroll
            for (int r = 0; r < 2; r++)
                #pragma unroll
                for (int hl = 0; hl < 2; hl++) {
                    sum[r][hl] += __shfl_xor_sync(0xffffffffu, sum[r][hl], 1);
                    sum[r][hl] += __shfl_xor_sync(0xffffffffu, sum[r][hl], 2);
                }
            __half2 rc[2][2];
            #pragma unroll
            for (int r = 0; r < 2; r++)
                #pragma unroll
                for (int hl = 0; hl < 2; hl++)
                    rc[r][hl] = __float2half2_rn(QSCALE / sum[r][hl]);
            #pragma unroll
            for (int nt = 0; nt < 4; nt++) {
                const int hl = nt >> 1;
                #pragma unroll
                for (int s2 = 0; s2 < 2; s2++) {
                    int cb = (th << 6) + (nt << 4) + (s2 << 3) + tq;
                    const int ei = (nt << 2) + (s2 << 1);
                    __half2 p0h = __hmul2(*(__half2*)&eh[ei], rc[0][hl]);
                    __half2 p1h = __hmul2(*(__half2*)&eh[ei + 1], rc[1][hl]);
                    *(uint32_t*)(sm + K2_BP + r0 * 272 + cb * 2) = *(uint32_t*)&p0h;
                    *(uint32_t*)(sm + K2_BP + r1 * 272 + cb * 2) = *(uint32_t*)&p1h;
                }
            }
        }
        const int nidx = idx + 1;
        const bool more = nidx < end;
        if (more) {
            const uint32_t dst = sb + (xoff ^ (K2_X0 ^ K2_X1));
            const uint4* src = (const uint4*)g_Xh + (size_t)nidx * 2176;
            for (int i = tid; i < 2176; i += 512)
                CP_ASYNC16(dst + (uint32_t)i * 16, src + i);
            CP_COMMIT();
        }
        __syncthreads();   // B2: Bp visible

        // ---- GEMM y: y[o][t] = sum_d G[o][d] * p[t][d] ----
        #pragma unroll
        for (int i = 0; i < 32; i++) acc[i] = 0.f;
        gemm_pass<8, 4>(acc, aG, b_lane_addr(sb, K2_BP + th * 17408u, lane));
        const int r0 = m0 + gp, r1 = r0 + 8;
        const float b0v = bs[r0], b1v = bs[r1];
        #pragma unroll
        for (int nt = 0; nt < 4; nt++) {
            #pragma unroll
            for (int s2 = 0; s2 < 2; s2++) {
                float* a4 = acc + (nt << 3) + (s2 << 2);
                a4[0] += b0v; a4[1] += b0v;
                a4[2] += b1v; a4[3] += b1v;
            }
        }
        // per-column y^2 partials
        {
            float pc[16];
            #pragma unroll
            for (int nt = 0; nt < 4; nt++) {
                #pragma unroll
                for (int s2 = 0; s2 < 2; s2++) {
                    const float* a4 = acc + (nt << 3) + (s2 << 2);
                    pc[(nt << 2) + (s2 << 1)]     = fmaf(a4[0], a4[0], a4[2] * a4[2]);
                    pc[(nt << 2) + (s2 << 1) + 1] = fmaf(a4[1], a4[1], a4[3] * a4[3]);
                }
            }
            #pragma unroll
            for (int i = 0; i < 16; i++) {
                pc[i] += __shfl_xor_sync(0xffffffffu, pc[i], 4);
                pc[i] += __shfl_xor_sync(0xffffffffu, pc[i], 8);
                pc[i] += __shfl_xor_sync(0xffffffffu, pc[i], 16);
            }
            if (lane < 4) {
                #pragma unroll
                for (int nt = 0; nt < 4; nt++) {
                    #pragma unroll
                    for (int s2 = 0; s2 < 2; s2++) {
                        int cb = (th << 6) + (nt << 4) + (s2 << 3) + tq;
                        psm[(cb << 3) + (w & 7)]       = pc[(nt << 2) + (s2 << 1)];
                        psm[((cb + 1) << 3) + (w & 7)] = pc[(nt << 2) + (s2 << 1) + 1];
                    }
                }
            }
        }
        __syncthreads();   // B3
        if (tid < 128) {
            float s = 0.f;
            #pragma unroll
            for (int k = 0; k < 8; k++) s += psm[(tid << 3) + k];
            invs[tid] = SQRTC / fmaxf(sqrtf(s), 1e-12f);
        }
        __syncthreads();   // B4
        // scale + store (streaming) from registers
        {
            const float g0 = g2s[r0], g1v = g2s[r1];
            float* ob0 = out + (((size_t)b) << 21) + ((size_t)r0 << 14) + p0;
            float* ob1 = out + (((size_t)b) << 21) + ((size_t)r1 << 14) + p0;
            #pragma unroll
            for (int nt = 0; nt < 4; nt++) {
                #pragma unroll
                for (int s2 = 0; s2 < 2; s2++) {
                    int cb = (th << 6) + (nt << 4) + (s2 << 3) + tq;
                    const float* a4 = acc + (nt << 3) + (s2 << 2);
                    float i0 = invs[cb], i1 = invs[cb + 1];
                    stcs2(ob0 + cb, make_float2(a4[0] * i0 * g0, a4[1] * i1 * g0));
                    stcs2(ob1 + cb, make_float2(a4[2] * i0 * g1v, a4[3] * i1 * g1v));
                }
            }
        }
        if (!more) return;
        idx = nidx;
        xoff ^= (K2_X0 ^ K2_X1);
    }
}

// ---------------------------------------------------------------------------
extern "C" void kernel_launch(void* const* d_in, const int* in_sizes, int n_in,
                              void* d_out, int out_size) {
    const float* x    = (const float*)d_in[0];
    const float* g1   = (const float*)d_in[1];
    const float* wqkv = (const float*)d_in[2];
    const float* wout = (const float*)d_in[3];
    const float* bout = (const float*)d_in[4];
    const float* g2   = (const float*)d_in[5];
    float* out = (float*)d_out;

    cudaFuncSetAttribute(qkv_kernel, cudaFuncAttributeMaxDynamicSharedMemorySize, K1_SMEM);
    cudaFuncSetAttribute(out_kernel, cudaFuncAttributeMaxDynamicSharedMemorySize, K2_SMEM);

    prep_kernel<<<256, 256>>>(wqkv, g1);
    qkv_kernel<<<GRID, 512, K1_SMEM>>>(x);
    out_kernel<<<GRID, 512, K2_SMEM>>>(wout, bout, g2, out);
}

// round 15
// speedup vs baseline: 1.3279x; 1.3279x over previous
#include <cuda_runtime.h>
#include <cuda_fp16.h>
#include <cstdint>
#include <math.h>

#define BB 16
#define CC 128
#define NN 16384
#define NTILES 2048
#define CHUNK 14
#define GRID 147
#define SQRTC 11.313708498984761f
#define QSCALE 0.17677669529663688f
#define L2E 1.4426950408889634f

// ---- global scratch ----
__device__ __align__(16) __half g_W16[3][128 * 136];
__device__ __align__(16) __half g_Xh[(size_t)2048 * 17408];
__device__ __align__(16) __half g_G[BB][128 * 136];
__device__ float g_ctx[BB * 4 * 32 * 32];
__device__ float g_den[BB * CC];

// =============================== helpers ==================================
__device__ __forceinline__ uint32_t smem_u32(const void* p) {
    uint32_t a;
    asm("{ .reg .u64 t; cvta.to.shared.u64 t, %1; cvt.u32.u64 %0, t; }" : "=r"(a) : "l"(p));
    return a;
}
__device__ __forceinline__ void ldsm4(uint32_t addr, uint32_t& r0, uint32_t& r1,
                                      uint32_t& r2, uint32_t& r3) {
    asm volatile("ldmatrix.sync.aligned.m8n8.x4.shared.b16 {%0,%1,%2,%3}, [%4];"
                 : "=r"(r0), "=r"(r1), "=r"(r2), "=r"(r3) : "r"(addr));
}
__device__ __forceinline__ void mma8(float* c, uint32_t a0, uint32_t a1, uint32_t a2,
                                     uint32_t a3, uint32_t b0, uint32_t b1) {
    asm volatile(
        "mma.sync.aligned.m16n8k16.row.col.f32.f16.f16.f32 "
        "{%0,%1,%2,%3},{%4,%5,%6,%7},{%8,%9},{%0,%1,%2,%3};"
        : "+f"(c[0]), "+f"(c[1]), "+f"(c[2]), "+f"(c[3])
        : "r"(a0), "r"(a1), "r"(a2), "r"(a3), "r"(b0), "r"(b1));
}
__device__ __forceinline__ uint32_t exp2_h2(float v0, float v1) {
    __half2 l = __floats2half2_rn(v0, v1);
    uint32_t e;
    asm("ex2.approx.f16x2 %0, %1;" : "=r"(e) : "r"(*(uint32_t*)&l));
    return e;
}
#define CP_ASYNC16(saddr, gptr) \
    asm volatile("cp.async.cg.shared.global [%0], [%1], 16;" :: "r"((uint32_t)(saddr)), "l"(gptr))
#define CP_COMMIT() asm volatile("cp.async.commit_group;" ::: "memory")
#define CP_WAIT0()  asm volatile("cp.async.wait_group 0;" ::: "memory")

template <int KSTEPS, int NT2>
__device__ __forceinline__ void gemm_pass(float* acc, uint32_t aLane, uint32_t bLane) {
    #pragma unroll
    for (int ks = 0; ks < KSTEPS; ks++) {
        uint32_t a0, a1, a2, a3;
        ldsm4(aLane + ks * 32, a0, a1, a2, a3);
        #pragma unroll
        for (int nt = 0; nt < NT2; nt++) {
            uint32_t b0, b1, b2, b3;
            ldsm4(bLane + nt * 4352 + ks * 32, b0, b1, b2, b3);
            mma8(acc + nt * 8,     a0, a1, a2, a3, b0, b1);
            mma8(acc + nt * 8 + 4, a0, a1, a2, a3, b2, b3);
        }
    }
}
template <int KSTEPS, int NT2>
__device__ __forceinline__ void gemm_dual(float* accA, float* accC,
                                          uint32_t aLane, uint32_t cLane, uint32_t bLane) {
    #pragma unroll
    for (int ks = 0; ks < KSTEPS; ks++) {
        uint32_t a0, a1, a2, a3, c0, c1, c2, c3;
        ldsm4(aLane + ks * 32, a0, a1, a2, a3);
        ldsm4(cLane + ks * 32, c0, c1, c2, c3);
        #pragma unroll
        for (int nt = 0; nt < NT2; nt++) {
            uint32_t b0, b1, b2, b3;
            ldsm4(bLane + nt * 4352 + ks * 32, b0, b1, b2, b3);
            mma8(accA + nt * 8,     a0, a1, a2, a3, b0, b1);
            mma8(accA + nt * 8 + 4, a0, a1, a2, a3, b2, b3);
            mma8(accC + nt * 8,     c0, c1, c2, c3, b0, b1);
            mma8(accC + nt * 8 + 4, c0, c1, c2, c3, b2, b3);
        }
    }
}
__device__ __forceinline__ uint32_t a_lane_addr(uint32_t sb, uint32_t off, int m0,
                                                int rs, int lane) {
    return sb + off + (uint32_t)(m0 + (lane & 15)) * rs + ((lane >> 4) << 4);
}
__device__ __forceinline__ uint32_t b_lane_addr(uint32_t sb, uint32_t off, int lane) {
    return sb + off + (uint32_t)((lane & 7) + ((lane & 16) >> 1)) * 272 + ((lane & 8) << 1);
}

// =============================== prep ======================================
__global__ void prep_kernel(const float* __restrict__ wqkv, const float* __restrict__ g1) {
    int i = blockIdx.x * 256 + threadIdx.x;
    if (i < 49152) {
        int g = i >> 14, r = i & 16383, o = r >> 7, c = r & 127;
        float v = wqkv[((g << 7) + o) * CC + c] * g1[c] * SQRTC;
        g_W16[g][o * 136 + c] = __float2half_rn(v);
    }
    if (i < BB * 4096) g_ctx[i] = 0.f;
    if (i < BB * CC)   g_den[i] = 0.f;
}

// =============================== K1 (persistent, chunked) ==================
#define K1_WK   0u
#define K1_WV   34816u
#define K1_X    69632u
#define K1_E    104448u
#define K1_V    139264u
#define K1_SMEM 174080

__global__ __launch_bounds__(512, 1) void qkv_kernel(const float* __restrict__ x) {
    extern __shared__ char sm[];
    const uint32_t sb = smem_u32(sm);
    const int tid = threadIdx.x, lane = tid & 31, w = tid >> 5;

    int idx = blockIdx.x * CHUNK;
    const int end = (idx + CHUNK < NTILES) ? idx + CHUNK : NTILES;
    if (idx >= NTILES) return;

    {
        const uint4* wsrc = (const uint4*)g_W16[1];
        uint4* wdst = (uint4*)(sm + K1_WK);
        for (int i = tid; i < 4352; i += 512) wdst[i] = wsrc[i];
    }
    const int t = tid >> 2, cq = tid & 3;
    const int m0 = (w & 7) << 4, th = w >> 3;
    const int gp = lane >> 2, tq = (lane & 3) << 1;
    const uint32_t bX = b_lane_addr(sb, K1_X + th * 17408u, lane);
    const uint32_t aWk = a_lane_addr(sb, K1_WK, m0, 272, lane);
    const uint32_t aWv = a_lane_addr(sb, K1_WV, m0, 272, lane);

    float xr[32];
    {
        const float* xb = x + ((size_t)(idx >> 7) << 21) + ((idx & 127) << 7) + t;
        #pragma unroll
        for (int j = 0; j < 32; j++) xr[j] = xb[(size_t)(cq * 32 + j) << 14];
    }

    while (true) {
        const int b = idx >> 7;
        float s = 0.f;
        #pragma unroll
        for (int j = 0; j < 32; j++) s = fmaf(xr[j], xr[j], s);
        s += __shfl_xor_sync(0xffffffffu, s, 1);
        s += __shfl_xor_sync(0xffffffffu, s, 2);
        const float it = 1.0f / fmaxf(sqrtf(s), 1e-12f);
        {
            uint32_t vals[16];
            #pragma unroll
            for (int j2 = 0; j2 < 16; j2++) {
                __half2 h = __floats2half2_rn(xr[2 * j2] * it, xr[2 * j2 + 1] * it);
                vals[j2] = *(uint32_t*)&h;
            }
            const uint32_t roff = (uint32_t)t * 272 + ((uint32_t)cq << 6);
            uint4* ps = (uint4*)(sm + K1_X + roff);
            uint4* pg = (uint4*)((char*)g_Xh + (size_t)idx * 34816 + roff);
            const uint4* v4 = (const uint4*)vals;
            #pragma unroll
            for (int j = 0; j < 4; j++) { ps[j] = v4[j]; pg[j] = v4[j]; }
        }
        __syncthreads();   // B1

        float acck[32], accv[32];
        #pragma unroll
        for (int i = 0; i < 32; i++) { acck[i] = 0.f; accv[i] = 0.f; }
        gemm_dual<8, 4>(acck, accv, aWk, aWv, bX);

        // epilogue k
        {
            const int r0 = m0 + gp, r1 = r0 + 8;
            float d0 = 0.f, d1 = 0.f;
            #pragma unroll
            for (int nt = 0; nt < 4; nt++) {
                #pragma unroll
                for (int s2 = 0; s2 < 2; s2++) {
                    int cb = (th << 6) + (nt << 4) + (s2 << 3) + tq;
                    const float* a4 = acck + (nt << 3) + (s2 << 2);
                    uint32_t e0 = exp2_h2(a4[0] * L2E, a4[1] * L2E);
                    uint32_t e1 = exp2_h2(a4[2] * L2E, a4[3] * L2E);
                    *(uint32_t*)(sm + K1_E + r0 * 272 + cb * 2) = e0;
                    *(uint32_t*)(sm + K1_E + r1 * 272 + cb * 2) = e1;
                    float2 f0 = __half22float2(*(__half2*)&e0);
                    float2 f1 = __half22float2(*(__half2*)&e1);
                    d0 += f0.x + f0.y;
                    d1 += f1.x + f1.y;
                }
            }
            d0 += __shfl_xor_sync(0xffffffffu, d0, 1);
            d0 += __shfl_xor_sync(0xffffffffu, d0, 2);
            d1 += __shfl_xor_sync(0xffffffffu, d1, 1);
            d1 += __shfl_xor_sync(0xffffffffu, d1, 2);
            if ((lane & 3) == 0) {
                atomicAdd(&g_den[(b << 7) + r0], d0);
                atomicAdd(&g_den[(b << 7) + r1], d1);
            }
        }
        const int nidx = idx + 1;
        const bool more = nidx < end;
        if (more) {
            const float* xb = x + ((size_t)(nidx >> 7) << 21) + ((nidx & 127) << 7) + t;
            #pragma unroll
            for (int j = 0; j < 32; j++) xr[j] = xb[(size_t)(cq * 32 + j) << 14];
        }
        // epilogue v
        {
            const int r0 = m0 + gp, r1 = r0 + 8;
            #pragma unroll
            for (int nt = 0; nt < 4; nt++) {
                #pragma unroll
                for (int s2 = 0; s2 < 2; s2++) {
                    int cb = (th << 6) + (nt << 4) + (s2 << 3) + tq;
                    const float* a4 = accv + (nt << 3) + (s2 << 2);
                    __half2 h0 = __floats2half2_rn(a4[0], a4[1]);
                    __half2 h1 = __floats2half2_rn(a4[2], a4[3]);
                    *(uint32_t*)(sm + K1_V + r0 * 272 + cb * 2) = *(uint32_t*)&h0;
                    *(uint32_t*)(sm + K1_V + r1 * 272 + cb * 2) = *(uint32_t*)&h1;
                }
            }
        }
        __syncthreads();   // B2
        // gram
        {
            const int h = (w & 7) >> 1;
            float acc16[16];
            #pragma unroll
            for (int i = 0; i < 16; i++) acc16[i] = 0.f;
            uint32_t aE = a_lane_addr(sb, K1_E, m0, 272, lane) + th * 128u;
            uint32_t bV = b_lane_addr(sb, K1_V + h * 8704u, lane) + th * 128u;
            gemm_pass<4, 2>(acc16, aE, bV);

            const int dl0 = (m0 + gp) & 31, dl1 = dl0 + 8;
            float* cbase = g_ctx + (((b << 2) + h) << 10);
            #pragma unroll
            for (int nt = 0; nt < 2; nt++) {
                #pragma unroll
                for (int s2 = 0; s2 < 2; s2++) {
                    int cb = (nt << 4) + (s2 << 3) + tq;
                    const float* a4 = acc16 + (nt << 3) + (s2 << 2);
                    atomicAdd(cbase + (dl0 << 5) + cb,     a4[0]);
                    atomicAdd(cbase + (dl0 << 5) + cb + 1, a4[1]);
                    atomicAdd(cbase + (dl1 << 5) + cb,     a4[2]);
                    atomicAdd(cbase + (dl1 << 5) + cb + 1, a4[3]);
                }
            }
        }
        if (!more) return;
        idx = nidx;
    }
}

// =============================== K1.5: G = Wo * ctxA =======================
__global__ __launch_bounds__(256, 1) void g_kernel(const float* __restrict__ wout) {
    __shared__ float ctxn[1024];
    __shared__ float invden[32];
    const int tid = threadIdx.x;
    const int b = blockIdx.x >> 2, h = blockIdx.x & 3;
    if (tid < 32) invden[tid] = 1.0f / g_den[(b << 7) + (h << 5) + tid];
    __syncthreads();
    #pragma unroll
    for (int j0 = 0; j0 < 4; j0++) {
        int j = tid + (j0 << 8);
        ctxn[j] = g_ctx[(b << 12) + (h << 10) + j] * invden[j >> 5];
    }
    __syncthreads();
    const int o = tid & 127, dh = (tid >> 7) << 4;
    float4 wr[8];
    const float4* wsrc = (const float4*)(wout + (o << 7) + (h << 5));
    #pragma unroll
    for (int j = 0; j < 8; j++) wr[j] = wsrc[j];
    #pragma unroll
    for (int dd = 0; dd < 16; dd++) {
        int d = dh + dd;
        const float4* cr = (const float4*)(ctxn + (d << 5));
        float a = 0.f;
        #pragma unroll
        for (int j = 0; j < 8; j++) {
            float4 c4 = cr[j];
            a = fmaf(wr[j].x, c4.x, a);
            a = fmaf(wr[j].y, c4.y, a);
            a = fmaf(wr[j].z, c4.z, a);
            a = fmaf(wr[j].w, c4.w, a);
        }
        g_G[b][o * 136 + (h << 5) + d] = __float2half_rn(a);
    }
}

// =============================== K2 (reg-softmax) ==========================
// regions: WQ@0 | X0@34816 | X1@69632 | G@104448 | BP@139264 | PS@174080
//          BIAS@178176 | G2@178688 | INVS@179200
#define K2_WQ   0u
#define K2_X0   34816u
#define K2_X1   69632u
#define K2_G    104448u
#define K2_BP   139264u
#define K2_PS   174080u
#define K2_BIAS 178176u
#define K2_G2   178688u
#define K2_INVS 179200u
#define K2_SMEM 179712

__global__ __launch_bounds__(512, 1) void out_kernel(const float* __restrict__ b_out,
                                                     const float* __restrict__ g2,
                                                     float* __restrict__ out) {
    extern __shared__ char sm[];
    const uint32_t sb = smem_u32(sm);
    const int tid = threadIdx.x, lane = tid & 31, w = tid >> 5;
    float* psm  = (float*)(sm + K2_PS);
    float* invs = (float*)(sm + K2_INVS);
    float* bs   = (float*)(sm + K2_BIAS);
    float* g2s  = (float*)(sm + K2_G2);

    int idx = blockIdx.x * CHUNK;
    const int end = (idx + CHUNK < NTILES) ? idx + CHUNK : NTILES;
    if (idx >= NTILES) return;

    {
        const uint4* wsrc = (const uint4*)g_W16[0];
        uint4* wdst = (uint4*)(sm + K2_WQ);
        for (int i = tid; i < 2176; i += 512) wdst[i] = wsrc[i];
        if (tid < 128) { bs[tid] = b_out[tid]; g2s[tid] = g2[tid]; }
    }
    const int m0 = (w & 7) << 4, th = w >> 3;
    const int gp = lane >> 2, tq = (lane & 3) << 1;
    const uint32_t aG  = a_lane_addr(sb, K2_G,  m0, 272, lane);
    const uint32_t bWq = b_lane_addr(sb, K2_WQ + th * 17408u, lane);

    uint32_t xoff = K2_X0;
    int prev_b = -1;
    {
        const uint4* src = (const uint4*)g_Xh + (size_t)idx * 2176;
        for (int i = tid; i < 2176; i += 512)
            CP_ASYNC16(sb + K2_X0 + (uint32_t)i * 16, src + i);
        CP_COMMIT();
    }

    while (true) {
        const int b = idx >> 7, p0 = (idx & 127) << 7;
        if (b != prev_b) {
            const uint4* gsrc = (const uint4*)g_G[b];
            uint4* gdst = (uint4*)(sm + K2_G);
            for (int i = tid; i < 2176; i += 512) gdst[i] = gsrc[i];
            prev_b = b;
        }
        CP_WAIT0();
        __syncthreads();   // B1: X + G visible; prior Bp reads drained

        // ---- GEMM q (A = X tokens-as-rows, B = Wq) -> logits in regs ----
        float acc[32];
        #pragma unroll
        for (int i = 0; i < 32; i++) acc[i] = 0.f;
        gemm_pass<8, 4>(acc, a_lane_addr(sb, xoff, m0, 272, lane), bWq);

        // prefetch next X-hat tile EARLY (hidden under softmax + y-GEMM)
        const int nidx = idx + 1;
        const bool more = nidx < end;
        if (more) {
            const uint32_t dst = sb + (xoff ^ (K2_X0 ^ K2_X1));
            const uint4* src = (const uint4*)g_Xh + (size_t)nidx * 2176;
            for (int i = tid; i < 2176; i += 512)
                CP_ASYNC16(dst + (uint32_t)i * 16, src + i);
            CP_COMMIT();
        }

        // ---- register softmax over d (head = 32 cols within lane quad) ----
        {
            const int r0 = m0 + gp, r1 = r0 + 8;
            float mx[2][2] = {{-1e30f, -1e30f}, {-1e30f, -1e30f}};
            #pragma unroll
            for (int nt = 0; nt < 4; nt++) {
                const int hl = nt >> 1;
                #pragma unroll
                for (int s2 = 0; s2 < 2; s2++) {
                    const float* a4 = acc + (nt << 3) + (s2 << 2);
                    mx[0][hl] = fmaxf(mx[0][hl], fmaxf(a4[0], a4[1]));
                    mx[1][hl] = fmaxf(mx[1][hl], fmaxf(a4[2], a4[3]));
                }
            }
            #pragma unroll
            for (int r = 0; r < 2; r++)
                #pragma unroll
                for (int hl = 0; hl < 2; hl++) {
                    mx[r][hl] = fmaxf(mx[r][hl], __shfl_xor_sync(0xffffffffu, mx[r][hl], 1));
                    mx[r][hl] = fmaxf(mx[r][hl], __shfl_xor_sync(0xffffffffu, mx[r][hl], 2));
                }
            uint32_t eh[16];
            float sum[2][2] = {{0.f, 0.f}, {0.f, 0.f}};
            #pragma unroll
            for (int nt = 0; nt < 4; nt++) {
                const int hl = nt >> 1;
                #pragma unroll
                for (int s2 = 0; s2 < 2; s2++) {
                    const float* a4 = acc + (nt << 3) + (s2 << 2);
                    const int ei = (nt << 2) + (s2 << 1);
                    eh[ei]     = exp2_h2((a4[0] - mx[0][hl]) * L2E, (a4[1] - mx[0][hl]) * L2E);
                    eh[ei + 1] = exp2_h2((a4[2] - mx[1][hl]) * L2E, (a4[3] - mx[1][hl]) * L2E);
                    float2 f0 = __half22float2(*(__half2*)&eh[ei]);
                    float2 f1 = __half22float2(*(__half2*)&eh[ei + 1]);
                    sum[0][hl] += f0.x + f0.y;
                    sum[1][hl] += f1.x + f1.y;
                }
            }
            #pragma unroll
            for (int r = 0; r < 2; r++)
                #pragma unroll
                for (int hl = 0; hl < 2; hl++) {
                    sum[r][hl] += __shfl_xor_sync(0xffffffffu, sum[r][hl], 1);
                    sum[r][hl] += __shfl_xor_sync(0xffffffffu, sum[r][hl], 2);
                }
            __half2 rc[2][2];
            #pragma unroll
            for (int r = 0; r < 2; r++)
                #pragma unroll
                for (int hl = 0; hl < 2; hl++)
                    rc[r][hl] = __float2half2_rn(QSCALE / sum[r][hl]);
            #pragma unroll
            for (int nt = 0; nt < 4; nt++) {
                const int hl = nt >> 1;
                #pragma unroll
                for (int s2 = 0; s2 < 2; s2++) {
                    int cb = (th << 6) + (nt << 4) + (s2 << 3) + tq;
                    const int ei = (nt << 2) + (s2 << 1);
                    __half2 p0h = __hmul2(*(__half2*)&eh[ei], rc[0][hl]);
                    __half2 p1h = __hmul2(*(__half2*)&eh[ei + 1], rc[1][hl]);
                    *(uint32_t*)(sm + K2_BP + r0 * 272 + cb * 2) = *(uint32_t*)&p0h;
                    *(uint32_t*)(sm + K2_BP + r1 * 272 + cb * 2) = *(uint32_t*)&p1h;
                }
            }
        }
        __syncthreads();   // B2: Bp visible

        // ---- GEMM y: y[o][t] = sum_d G[o][d] * p[t][d] ----
        #pragma unroll
        for (int i = 0; i < 32; i++) acc[i] = 0.f;
        gemm_pass<8, 4>(acc, aG, b_lane_addr(sb, K2_BP + th * 17408u, lane));
        const int r0 = m0 + gp, r1 = r0 + 8;
        const float b0v = bs[r0], b1v = bs[r1];
        #pragma unroll
        for (int nt = 0; nt < 4; nt++) {
            #pragma unroll
            for (int s2 = 0; s2 < 2; s2++) {
                float* a4 = acc + (nt << 3) + (s2 << 2);
                a4[0] += b0v; a4[1] += b0v;
                a4[2] += b1v; a4[3] += b1v;
            }
        }
        // per-column y^2 partials
        {
            float pc[16];
            #pragma unroll
            for (int nt = 0; nt < 4; nt++) {
                #pragma unroll
                for (int s2 = 0; s2 < 2; s2++) {
                    const float* a4 = acc + (nt << 3) + (s2 << 2);
                    pc[(nt << 2) + (s2 << 1)]     = fmaf(a4[0], a4[0], a4[2] * a4[2]);
                    pc[(nt << 2) + (s2 << 1) + 1] = fmaf(a4[1], a4[1], a4[3] * a4[3]);
                }
            }
            #pragma unroll
            for (int i = 0; i < 16; i++) {
                pc[i] += __shfl_xor_sync(0xffffffffu, pc[i], 4);
                pc[i] += __shfl_xor_sync(0xffffffffu, pc[i], 8);
                pc[i] += __shfl_xor_sync(0xffffffffu, pc[i], 16);
            }
            if (lane < 4) {
                #pragma unroll
                for (int nt = 0; nt < 4; nt++) {
                    #pragma unroll
                    for (int s2 = 0; s2 < 2; s2++) {
                        int cb = (th << 6) + (nt << 4) + (s2 << 3) + tq;
                        psm[(cb << 3) + (w & 7)]       = pc[(nt << 2) + (s2 << 1)];
                        psm[((cb + 1) << 3) + (w & 7)] = pc[(nt << 2) + (s2 << 1) + 1];
                    }
                }
            }
        }
        __syncthreads();   // B3
        if (tid < 128) {
            float s = 0.f;
            #pragma unroll
            for (int k = 0; k < 8; k++) s += psm[(tid << 3) + k];
            invs[tid] = SQRTC / fmaxf(sqrtf(s), 1e-12f);
        }
        __syncthreads();   // B4
        // scale + store from registers
        {
            const float g0 = g2s[r0], g1v = g2s[r1];
            float* ob0 = out + (((size_t)b) << 21) + ((size_t)r0 << 14) + p0;
            float* ob1 = out + (((size_t)b) << 21) + ((size_t)r1 << 14) + p0;
            #pragma unroll
            for (int nt = 0; nt < 4; nt++) {
                #pragma unroll
                for (int s2 = 0; s2 < 2; s2++) {
                    int cb = (th << 6) + (nt << 4) + (s2 << 3) + tq;
                    const float* a4 = acc + (nt << 3) + (s2 << 2);
                    float i0 = invs[cb], i1 = invs[cb + 1];
                    *(float2*)(ob0 + cb) = make_float2(a4[0] * i0 * g0, a4[1] * i1 * g0);
                    *(float2*)(ob1 + cb) = make_float2(a4[2] * i0 * g1v, a4[3] * i1 * g1v);
                }
            }
        }
        if (!more) return;
        idx = nidx;
        xoff ^= (K2_X0 ^ K2_X1);
    }
}

// ---------------------------------------------------------------------------
extern "C" void kernel_launch(void* const* d_in, const int* in_sizes, int n_in,
                              void* d_out, int out_size) {
    const float* x    = (const float*)d_in[0];
    const float* g1   = (const float*)d_in[1];
    const float* wqkv = (const float*)d_in[2];
    const float* wout = (const float*)d_in[3];
    const float* bout = (const float*)d_in[4];
    const float* g2   = (const float*)d_in[5];
    float* out = (float*)d_out;

    cudaFuncSetAttribute(qkv_kernel, cudaFuncAttributeMaxDynamicSharedMemorySize, K1_SMEM);
    cudaFuncSetAttribute(out_kernel, cudaFuncAttributeMaxDynamicSharedMemorySize, K2_SMEM);

    prep_kernel<<<256, 256>>>(wqkv, g1);
    qkv_kernel<<<GRID, 512, K1_SMEM>>>(x);
    g_kernel<<<64, 256>>>(wout);
    out_kernel<<<GRID, 512, K2_SMEM>>>(bout, g2, out);
}

// round 16
// speedup vs baseline: 1.3358x; 1.0060x over previous
#include <cuda_runtime.h>
#include <cuda_fp16.h>
#include <cstdint>
#include <math.h>

#define BB 16
#define CC 128
#define NN 16384
#define NTILES 2048
#define CHUNK 14
#define GRID 147
#define SQRTC 11.313708498984761f
#define QSCALE 0.17677669529663688f
#define L2E 1.4426950408889634f

// ---- global scratch ----
__device__ __align__(16) __half g_W16[3][128 * 136];
__device__ __align__(16) __half g_Xh[(size_t)2048 * 17408];
__device__ __align__(16) __half g_G[BB][128 * 136];
__device__ float g_ctx[BB * 4 * 32 * 32];
__device__ float g_den[BB * CC];

// =============================== helpers ==================================
__device__ __forceinline__ uint32_t smem_u32(const void* p) {
    uint32_t a;
    asm("{ .reg .u64 t; cvta.to.shared.u64 t, %1; cvt.u32.u64 %0, t; }" : "=r"(a) : "l"(p));
    return a;
}
__device__ __forceinline__ void ldsm4(uint32_t addr, uint32_t& r0, uint32_t& r1,
                                      uint32_t& r2, uint32_t& r3) {
    asm volatile("ldmatrix.sync.aligned.m8n8.x4.shared.b16 {%0,%1,%2,%3}, [%4];"
                 : "=r"(r0), "=r"(r1), "=r"(r2), "=r"(r3) : "r"(addr));
}
__device__ __forceinline__ void mma8(float* c, uint32_t a0, uint32_t a1, uint32_t a2,
                                     uint32_t a3, uint32_t b0, uint32_t b1) {
    asm volatile(
        "mma.sync.aligned.m16n8k16.row.col.f32.f16.f16.f32 "
        "{%0,%1,%2,%3},{%4,%5,%6,%7},{%8,%9},{%0,%1,%2,%3};"
        : "+f"(c[0]), "+f"(c[1]), "+f"(c[2]), "+f"(c[3])
        : "r"(a0), "r"(a1), "r"(a2), "r"(a3), "r"(b0), "r"(b1));
}
__device__ __forceinline__ uint32_t exp2_h2(float v0, float v1) {
    __half2 l = __floats2half2_rn(v0, v1);
    uint32_t e;
    asm("ex2.approx.f16x2 %0, %1;" : "=r"(e) : "r"(*(uint32_t*)&l));
    return e;
}
#define CP_ASYNC16(saddr, gptr) \
    asm volatile("cp.async.cg.shared.global [%0], [%1], 16;" :: "r"((uint32_t)(saddr)), "l"(gptr))
#define CP_COMMIT() asm volatile("cp.async.commit_group;" ::: "memory")
#define CP_WAIT0()  asm volatile("cp.async.wait_group 0;" ::: "memory")

template <int KSTEPS, int NT2>
__device__ __forceinline__ void gemm_pass(float* acc, uint32_t aLane, uint32_t bLane) {
    #pragma unroll
    for (int ks = 0; ks < KSTEPS; ks++) {
        uint32_t a0, a1, a2, a3;
        ldsm4(aLane + ks * 32, a0, a1, a2, a3);
        #pragma unroll
        for (int nt = 0; nt < NT2; nt++) {
            uint32_t b0, b1, b2, b3;
            ldsm4(bLane + nt * 4352 + ks * 32, b0, b1, b2, b3);
            mma8(acc + nt * 8,     a0, a1, a2, a3, b0, b1);
            mma8(acc + nt * 8 + 4, a0, a1, a2, a3, b2, b3);
        }
    }
}
template <int KSTEPS, int NT2>
__device__ __forceinline__ void gemm_dual(float* accA, float* accC,
                                          uint32_t aLane, uint32_t cLane, uint32_t bLane) {
    #pragma unroll
    for (int ks = 0; ks < KSTEPS; ks++) {
        uint32_t a0, a1, a2, a3, c0, c1, c2, c3;
        ldsm4(aLane + ks * 32, a0, a1, a2, a3);
        ldsm4(cLane + ks * 32, c0, c1, c2, c3);
        #pragma unroll
        for (int nt = 0; nt < NT2; nt++) {
            uint32_t b0, b1, b2, b3;
            ldsm4(bLane + nt * 4352 + ks * 32, b0, b1, b2, b3);
            mma8(accA + nt * 8,     a0, a1, a2, a3, b0, b1);
            mma8(accA + nt * 8 + 4, a0, a1, a2, a3, b2, b3);
            mma8(accC + nt * 8,     c0, c1, c2, c3, b0, b1);
            mma8(accC + nt * 8 + 4, c0, c1, c2, c3, b2, b3);
        }
    }
}
__device__ __forceinline__ uint32_t a_lane_addr(uint32_t sb, uint32_t off, int m0,
                                                int rs, int lane) {
    return sb + off + (uint32_t)(m0 + (lane & 15)) * rs + ((lane >> 4) << 4);
}
__device__ __forceinline__ uint32_t b_lane_addr(uint32_t sb, uint32_t off, int lane) {
    return sb + off + (uint32_t)((lane & 7) + ((lane & 16) >> 1)) * 272 + ((lane & 8) << 1);
}

// =============================== prep ======================================
__global__ void prep_kernel(const float* __restrict__ wqkv, const float* __restrict__ g1) {
    int i = blockIdx.x * 256 + threadIdx.x;
    if (i < 49152) {
        int g = i >> 14, r = i & 16383, o = r >> 7, c = r & 127;
        float v = wqkv[((g << 7) + o) * CC + c] * g1[c] * SQRTC;
        g_W16[g][o * 136 + c] = __float2half_rn(v);
    }
    if (i < BB * 4096) g_ctx[i] = 0.f;
    if (i < BB * CC)   g_den[i] = 0.f;
}

// =============================== K1 (persistent, chunked) ==================
#define K1_WK   0u
#define K1_WV   34816u
#define K1_X    69632u
#define K1_E    104448u
#define K1_V    139264u
#define K1_SMEM 174080

__global__ __launch_bounds__(512, 1) void qkv_kernel(const float* __restrict__ x) {
    extern __shared__ char sm[];
    const uint32_t sb = smem_u32(sm);
    const int tid = threadIdx.x, lane = tid & 31, w = tid >> 5;

    int idx = blockIdx.x * CHUNK;
    const int end = (idx + CHUNK < NTILES) ? idx + CHUNK : NTILES;
    if (idx >= NTILES) return;

    {
        const uint4* wsrc = (const uint4*)g_W16[1];
        uint4* wdst = (uint4*)(sm + K1_WK);
        for (int i = tid; i < 4352; i += 512) wdst[i] = wsrc[i];
    }
    const int t = tid >> 2, cq = tid & 3;
    const int m0 = (w & 7) << 4, th = w >> 3;
    const int gp = lane >> 2, tq = (lane & 3) << 1;
    const uint32_t bX = b_lane_addr(sb, K1_X + th * 17408u, lane);
    const uint32_t aWk = a_lane_addr(sb, K1_WK, m0, 272, lane);
    const uint32_t aWv = a_lane_addr(sb, K1_WV, m0, 272, lane);

    float xr[32];
    {
        const float* xb = x + ((size_t)(idx >> 7) << 21) + ((idx & 127) << 7) + t;
        #pragma unroll
        for (int j = 0; j < 32; j++) xr[j] = xb[(size_t)(cq * 32 + j) << 14];
    }

    while (true) {
        const int b = idx >> 7;
        float s = 0.f;
        #pragma unroll
        for (int j = 0; j < 32; j++) s = fmaf(xr[j], xr[j], s);
        s += __shfl_xor_sync(0xffffffffu, s, 1);
        s += __shfl_xor_sync(0xffffffffu, s, 2);
        const float it = 1.0f / fmaxf(sqrtf(s), 1e-12f);
        {
            uint32_t vals[16];
            #pragma unroll
            for (int j2 = 0; j2 < 16; j2++) {
                __half2 h = __floats2half2_rn(xr[2 * j2] * it, xr[2 * j2 + 1] * it);
                vals[j2] = *(uint32_t*)&h;
            }
            const uint32_t roff = (uint32_t)t * 272 + ((uint32_t)cq << 6);
            uint4* ps = (uint4*)(sm + K1_X + roff);
            uint4* pg = (uint4*)((char*)g_Xh + (size_t)idx * 34816 + roff);
            const uint4* v4 = (const uint4*)vals;
            #pragma unroll
            for (int j = 0; j < 4; j++) { ps[j] = v4[j]; pg[j] = v4[j]; }
        }
        __syncthreads();   // B1

        float acck[32], accv[32];
        #pragma unroll
        for (int i = 0; i < 32; i++) { acck[i] = 0.f; accv[i] = 0.f; }
        gemm_dual<8, 4>(acck, accv, aWk, aWv, bX);

        // epilogue k
        {
            const int r0 = m0 + gp, r1 = r0 + 8;
            float d0 = 0.f, d1 = 0.f;
            #pragma unroll
            for (int nt = 0; nt < 4; nt++) {
                #pragma unroll
                for (int s2 = 0; s2 < 2; s2++) {
                    int cb = (th << 6) + (nt << 4) + (s2 << 3) + tq;
                    const float* a4 = acck + (nt << 3) + (s2 << 2);
                    uint32_t e0 = exp2_h2(a4[0] * L2E, a4[1] * L2E);
                    uint32_t e1 = exp2_h2(a4[2] * L2E, a4[3] * L2E);
                    *(uint32_t*)(sm + K1_E + r0 * 272 + cb * 2) = e0;
                    *(uint32_t*)(sm + K1_E + r1 * 272 + cb * 2) = e1;
                    float2 f0 = __half22float2(*(__half2*)&e0);
                    float2 f1 = __half22float2(*(__half2*)&e1);
                    d0 += f0.x + f0.y;
                    d1 += f1.x + f1.y;
                }
            }
            d0 += __shfl_xor_sync(0xffffffffu, d0, 1);
            d0 += __shfl_xor_sync(0xffffffffu, d0, 2);
            d1 += __shfl_xor_sync(0xffffffffu, d1, 1);
            d1 += __shfl_xor_sync(0xffffffffu, d1, 2);
            if ((lane & 3) == 0) {
                atomicAdd(&g_den[(b << 7) + r0], d0);
                atomicAdd(&g_den[(b << 7) + r1], d1);
            }
        }
        const int nidx = idx + 1;
        const bool more = nidx < end;
        if (more) {
            const float* xb = x + ((size_t)(nidx >> 7) << 21) + ((nidx & 127) << 7) + t;
            #pragma unroll
            for (int j = 0; j < 32; j++) xr[j] = xb[(size_t)(cq * 32 + j) << 14];
        }
        // epilogue v
        {
            const int r0 = m0 + gp, r1 = r0 + 8;
            #pragma unroll
            for (int nt = 0; nt < 4; nt++) {
                #pragma unroll
                for (int s2 = 0; s2 < 2; s2++) {
                    int cb = (th << 6) + (nt << 4) + (s2 << 3) + tq;
                    const float* a4 = accv + (nt << 3) + (s2 << 2);
                    __half2 h0 = __floats2half2_rn(a4[0], a4[1]);
                    __half2 h1 = __floats2half2_rn(a4[2], a4[3]);
                    *(uint32_t*)(sm + K1_V + r0 * 272 + cb * 2) = *(uint32_t*)&h0;
                    *(uint32_t*)(sm + K1_V + r1 * 272 + cb * 2) = *(uint32_t*)&h1;
                }
            }
        }
        __syncthreads();   // B2
        // gram
        {
            const int h = (w & 7) >> 1;
            float acc16[16];
            #pragma unroll
            for (int i = 0; i < 16; i++) acc16[i] = 0.f;
            uint32_t aE = a_lane_addr(sb, K1_E, m0, 272, lane) + th * 128u;
            uint32_t bV = b_lane_addr(sb, K1_V + h * 8704u, lane) + th * 128u;
            gemm_pass<4, 2>(acc16, aE, bV);

            const int dl0 = (m0 + gp) & 31, dl1 = dl0 + 8;
            float* cbase = g_ctx + (((b << 2) + h) << 10);
            #pragma unroll
            for (int nt = 0; nt < 2; nt++) {
                #pragma unroll
                for (int s2 = 0; s2 < 2; s2++) {
                    int cb = (nt << 4) + (s2 << 3) + tq;
                    const float* a4 = acc16 + (nt << 3) + (s2 << 2);
                    atomicAdd(cbase + (dl0 << 5) + cb,     a4[0]);
                    atomicAdd(cbase + (dl0 << 5) + cb + 1, a4[1]);
                    atomicAdd(cbase + (dl1 << 5) + cb,     a4[2]);
                    atomicAdd(cbase + (dl1 << 5) + cb + 1, a4[3]);
                }
            }
        }
        if (!more) return;
        idx = nidx;
    }
}

// =============================== K1.5: G = Wo * ctxA =======================
__global__ __launch_bounds__(256, 1) void g_kernel(const float* __restrict__ wout) {
    __shared__ float ctxn[1024];
    __shared__ float invden[32];
    const int tid = threadIdx.x;
    const int b = blockIdx.x >> 2, h = blockIdx.x & 3;
    if (tid < 32) invden[tid] = 1.0f / g_den[(b << 7) + (h << 5) + tid];
    __syncthreads();
    #pragma unroll
    for (int j0 = 0; j0 < 4; j0++) {
        int j = tid + (j0 << 8);
        ctxn[j] = g_ctx[(b << 12) + (h << 10) + j] * invden[j >> 5];
    }
    __syncthreads();
    const int o = tid & 127, dh = (tid >> 7) << 4;
    float4 wr[8];
    const float4* wsrc = (const float4*)(wout + (o << 7) + (h << 5));
    #pragma unroll
    for (int j = 0; j < 8; j++) wr[j] = wsrc[j];
    #pragma unroll
    for (int dd = 0; dd < 16; dd++) {
        int d = dh + dd;
        const float4* cr = (const float4*)(ctxn + (d << 5));
        float a = 0.f;
        #pragma unroll
        for (int j = 0; j < 8; j++) {
            float4 c4 = cr[j];
            a = fmaf(wr[j].x, c4.x, a);
            a = fmaf(wr[j].y, c4.y, a);
            a = fmaf(wr[j].z, c4.z, a);
            a = fmaf(wr[j].w, c4.w, a);
        }
        g_G[b][o * 136 + (h << 5) + d] = __float2half_rn(a);
    }
}

// =============================== K2 (reg-softmax, no-max) ==================
// regions: WQ@0 | X0@34816 | X1@69632 | G@104448 | BP@139264 | PS@174080
//          BIAS@178176 | G2@178688 | INVS@179200
#define K2_WQ   0u
#define K2_X0   34816u
#define K2_X1   69632u
#define K2_G    104448u
#define K2_BP   139264u
#define K2_PS   174080u
#define K2_BIAS 178176u
#define K2_G2   178688u
#define K2_INVS 179200u
#define K2_SMEM 179712

__global__ __launch_bounds__(512, 1) void out_kernel(const float* __restrict__ b_out,
                                                     const float* __restrict__ g2,
                                                     float* __restrict__ out) {
    extern __shared__ char sm[];
    const uint32_t sb = smem_u32(sm);
    const int tid = threadIdx.x, lane = tid & 31, w = tid >> 5;
    float* psm  = (float*)(sm + K2_PS);
    float* invs = (float*)(sm + K2_INVS);
    float* bs   = (float*)(sm + K2_BIAS);
    float* g2s  = (float*)(sm + K2_G2);

    int idx = blockIdx.x * CHUNK;
    const int end = (idx + CHUNK < NTILES) ? idx + CHUNK : NTILES;
    if (idx >= NTILES) return;

    {
        const uint4* wsrc = (const uint4*)g_W16[0];
        uint4* wdst = (uint4*)(sm + K2_WQ);
        for (int i = tid; i < 2176; i += 512) wdst[i] = wsrc[i];
        if (tid < 128) { bs[tid] = b_out[tid]; g2s[tid] = g2[tid]; }
    }
    const int m0 = (w & 7) << 4, th = w >> 3;
    const int gp = lane >> 2, tq = (lane & 3) << 1;
    const uint32_t aG  = a_lane_addr(sb, K2_G,  m0, 272, lane);
    const uint32_t bWq = b_lane_addr(sb, K2_WQ + th * 17408u, lane);

    uint32_t xoff = K2_X0;
    int prev_b = -1;
    {
        const uint4* src = (const uint4*)g_Xh + (size_t)idx * 2176;
        for (int i = tid; i < 2176; i += 512)
            CP_ASYNC16(sb + K2_X0 + (uint32_t)i * 16, src + i);
        CP_COMMIT();
    }

    while (true) {
        const int b = idx >> 7, p0 = (idx & 127) << 7;
        if (b != prev_b) {
            const uint4* gsrc = (const uint4*)g_G[b];
            uint4* gdst = (uint4*)(sm + K2_G);
            for (int i = tid; i < 2176; i += 512) gdst[i] = gsrc[i];
            prev_b = b;
        }
        CP_WAIT0();
        __syncthreads();   // B1: X + G visible; prior Bp reads drained

        // ---- GEMM q (A = X tokens-as-rows, B = Wq) -> logits in regs ----
        float acc[32];
        #pragma unroll
        for (int i = 0; i < 32; i++) acc[i] = 0.f;
        gemm_pass<8, 4>(acc, a_lane_addr(sb, xoff, m0, 272, lane), bWq);

        // prefetch next X-hat tile EARLY (hidden under softmax + y-GEMM)
        const int nidx = idx + 1;
        const bool more = nidx < end;
        if (more) {
            const uint32_t dst = sb + (xoff ^ (K2_X0 ^ K2_X1));
            const uint4* src = (const uint4*)g_Xh + (size_t)nidx * 2176;
            for (int i = tid; i < 2176; i += 512)
                CP_ASYNC16(dst + (uint32_t)i * 16, src + i);
            CP_COMMIT();
        }

        // ---- register softmax over d (no max-subtraction; same policy as k-path) ----
        {
            const int r0 = m0 + gp, r1 = r0 + 8;
            uint32_t eh[16];
            float sum[2][2] = {{0.f, 0.f}, {0.f, 0.f}};
            #pragma unroll
            for (int nt = 0; nt < 4; nt++) {
                const int hl = nt >> 1;
                #pragma unroll
                for (int s2 = 0; s2 < 2; s2++) {
                    const float* a4 = acc + (nt << 3) + (s2 << 2);
                    const int ei = (nt << 2) + (s2 << 1);
                    eh[ei]     = exp2_h2(a4[0] * L2E, a4[1] * L2E);
                    eh[ei + 1] = exp2_h2(a4[2] * L2E, a4[3] * L2E);
                    float2 f0 = __half22float2(*(__half2*)&eh[ei]);
                    float2 f1 = __half22float2(*(__half2*)&eh[ei + 1]);
                    sum[0][hl] += f0.x + f0.y;
                    sum[1][hl] += f1.x + f1.y;
                }
            }
            #pragma unroll
            for (int r = 0; r < 2; r++)
                #pragma unroll
                for (int hl = 0; hl < 2; hl++) {
                    sum[r][hl] += __shfl_xor_sync(0xffffffffu, sum[r][hl], 1);
                    sum[r][hl] += __shfl_xor_sync(0xffffffffu, sum[r][hl], 2);
                }
            __half2 rc[2][2];
            #pragma unroll
            for (int r = 0; r < 2; r++)
                #pragma unroll
                for (int hl = 0; hl < 2; hl++)
                    rc[r][hl] = __float2half2_rn(QSCALE / sum[r][hl]);
            #pragma unroll
            for (int nt = 0; nt < 4; nt++) {
                const int hl = nt >> 1;
                #pragma unroll
                for (int s2 = 0; s2 < 2; s2++) {
                    int cb = (th << 6) + (nt << 4) + (s2 << 3) + tq;
                    const int ei = (nt << 2) + (s2 << 1);
                    __half2 p0h = __hmul2(*(__half2*)&eh[ei], rc[0][hl]);
                    __half2 p1h = __hmul2(*(__half2*)&eh[ei + 1], rc[1][hl]);
                    *(uint32_t*)(sm + K2_BP + r0 * 272 + cb * 2) = *(uint32_t*)&p0h;
                    *(uint32_t*)(sm + K2_BP + r1 * 272 + cb * 2) = *(uint32_t*)&p1h;
                }
            }
        }
        __syncthreads();   // B2: Bp visible

        // ---- GEMM y: y[o][t] = sum_d G[o][d] * p[t][d] ----
        #pragma unroll
        for (int i = 0; i < 32; i++) acc[i] = 0.f;
        gemm_pass<8, 4>(acc, aG, b_lane_addr(sb, K2_BP + th * 17408u, lane));
        const int r0 = m0 + gp, r1 = r0 + 8;
        const float b0v = bs[r0], b1v = bs[r1];
        #pragma unroll
        for (int nt = 0; nt < 4; nt++) {
            #pragma unroll
            for (int s2 = 0; s2 < 2; s2++) {
                float* a4 = acc + (nt << 3) + (s2 << 2);
                a4[0] += b0v; a4[1] += b0v;
                a4[2] += b1v; a4[3] += b1v;
            }
        }
        // per-column y^2 partials
        {
            float pc[16];
            #pragma unroll
            for (int nt = 0; nt < 4; nt++) {
                #pragma unroll
                for (int s2 = 0; s2 < 2; s2++) {
                    const float* a4 = acc + (nt << 3) + (s2 << 2);
                    pc[(nt << 2) + (s2 << 1)]     = fmaf(a4[0], a4[0], a4[2] * a4[2]);
                    pc[(nt << 2) + (s2 << 1) + 1] = fmaf(a4[1], a4[1], a4[3] * a4[3]);
                }
            }
            #pragma unroll
            for (int i = 0; i < 16; i++) {
                pc[i] += __shfl_xor_sync(0xffffffffu, pc[i], 4);
                pc[i] += __shfl_xor_sync(0xffffffffu, pc[i], 8);
                pc[i] += __shfl_xor_sync(0xffffffffu, pc[i], 16);
            }
            if (lane < 4) {
                #pragma unroll
                for (int nt = 0; nt < 4; nt++) {
                    #pragma unroll
                    for (int s2 = 0; s2 < 2; s2++) {
                        int cb = (th << 6) + (nt << 4) + (s2 << 3) + tq;
                        psm[(cb << 3) + (w & 7)]       = pc[(nt << 2) + (s2 << 1)];
                        psm[((cb + 1) << 3) + (w & 7)] = pc[(nt << 2) + (s2 << 1) + 1];
                    }
                }
            }
        }
        __syncthreads();   // B3
        if (tid < 128) {
            float s = 0.f;
            #pragma unroll
            for (int k = 0; k < 8; k++) s += psm[(tid << 3) + k];
            invs[tid] = SQRTC / fmaxf(sqrtf(s), 1e-12f);
        }
        __syncthreads();   // B4
        // scale + store from registers
        {
            const float g0 = g2s[r0], g1v = g2s[r1];
            float* ob0 = out + (((size_t)b) << 21) + ((size_t)r0 << 14) + p0;
            float* ob1 = out + (((size_t)b) << 21) + ((size_t)r1 << 14) + p0;
            #pragma unroll
            for (int nt = 0; nt < 4; nt++) {
                #pragma unroll
                for (int s2 = 0; s2 < 2; s2++) {
                    int cb = (th << 6) + (nt << 4) + (s2 << 3) + tq;
                    const float* a4 = acc + (nt << 3) + (s2 << 2);
                    float i0 = invs[cb], i1 = invs[cb + 1];
                    *(float2*)(ob0 + cb) = make_float2(a4[0] * i0 * g0, a4[1] * i1 * g0);
                    *(float2*)(ob1 + cb) = make_float2(a4[2] * i0 * g1v, a4[3] * i1 * g1v);
                }
            }
        }
        if (!more) return;
        idx = nidx;
        xoff ^= (K2_X0 ^ K2_X1);
    }
}

// ---------------------------------------------------------------------------
extern "C" void kernel_launch(void* const* d_in, const int* in_sizes, int n_in,
                              void* d_out, int out_size) {
    const float* x    = (const float*)d_in[0];
    const float* g1   = (const float*)d_in[1];
    const float* wqkv = (const float*)d_in[2];
    const float* wout = (const float*)d_in[3];
    const float* bout = (const float*)d_in[4];
    const float* g2   = (const float*)d_in[5];
    float* out = (float*)d_out;

    cudaFuncSetAttribute(qkv_kernel, cudaFuncAttributeMaxDynamicSharedMemorySize, K1_SMEM);
    cudaFuncSetAttribute(out_kernel, cudaFuncAttributeMaxDynamicSharedMemorySize, K2_SMEM);

    prep_kernel<<<256, 256>>>(wqkv, g1);
    qkv_kernel<<<GRID, 512, K1_SMEM>>>(x);
    g_kernel<<<64, 256>>>(wout);
    out_kernel<<<GRID, 512, K2_SMEM>>>(bout, g2, out);
}